// round 8
// baseline (speedup 1.0000x reference)
#include <cuda_runtime.h>
#include <cstdint>
#include <math_constants.h>

#define N_ROWS   8192
#define K_CODES  8192
#define D_DIM    512
#define NGROUPS  (K_CODES / 32)    // 256 column groups of 32 codes

// Output layout: [quantized (4194304) | loss (1) | indices (8192) | min_dist (8192) | loss_commit (1)]
#define QUANT_OFF  0
#define LOSS_OFF   (N_ROWS * D_DIM)
#define IDX_OFF    (LOSS_OFF + 1)
#define MIND_OFF   (IDX_OFF + N_ROWS)
#define COMMIT_OFF (MIND_OFF + N_ROWS)

// int8 quantization scale: clamp at ±127/21 = ±6.05 sigma
#define QSCALE   21.0f
#define DEQ2     (2.0f / (QSCALE * QSCALE))    // 2/441

// ---------------- device scratch ----------------
__device__ uint8_t g_Xq[N_ROWS * D_DIM];     // int8 inputs
__device__ uint8_t g_Eq[K_CODES * D_DIM];    // int8 codebook
__device__ unsigned long long g_gmin[(size_t)N_ROWS * NGROUPS];  // 16MB packed (score,idx)
__device__ float g_cbn[K_CODES];
__device__ float g_xn[N_ROWS];
__device__ float g_row_partial[N_ROWS];

// ---------------- helpers ----------------
__device__ __forceinline__ uint32_t smem_u32(const void* p) {
    uint32_t a;
    asm("{ .reg .u64 t; cvta.to.shared.u64 t, %1; cvt.u32.u64 %0, t; }" : "=r"(a) : "l"(p));
    return a;
}
#define CP16(dst, src) \
    asm volatile("cp.async.cg.shared.global [%0], [%1], 16;" :: "r"(dst), "l"(src))
#define CP_COMMIT() asm volatile("cp.async.commit_group;" ::: "memory")
#define CP_WAIT1()  asm volatile("cp.async.wait_group 1;" ::: "memory")
#define CP_WAIT0()  asm volatile("cp.async.wait_group 0;" ::: "memory")

#define LDSM4(r0, r1, r2, r3, addr) \
    asm volatile("ldmatrix.sync.aligned.m8n8.x4.shared.b16 {%0,%1,%2,%3}, [%4];" \
        : "=r"(r0), "=r"(r1), "=r"(r2), "=r"(r3) : "r"(addr))

// int8 IMMA: m16n8k32, fragment byte-layout identical to the (verified) fp8 path
#define IMMA(c, a, b0, b1) \
    asm volatile("mma.sync.aligned.m16n8k32.row.col.s32.s8.s8.s32 " \
        "{%0,%1,%2,%3}, {%4,%5,%6,%7}, {%8,%9}, {%0,%1,%2,%3};" \
        : "+r"((c)[0]), "+r"((c)[1]), "+r"((c)[2]), "+r"((c)[3]) \
        : "r"((a)[0]), "r"((a)[1]), "r"((a)[2]), "r"((a)[3]), "r"(b0), "r"(b1))

__device__ __forceinline__ int q8(float v) {
    int q = __float2int_rn(v * QSCALE);
    return max(-127, min(127, q));
}
__device__ __forceinline__ uint32_t pack_s8x4(float v0, float v1, float v2, float v3) {
    return (uint32_t)(q8(v0) & 0xFF) | ((uint32_t)(q8(v1) & 0xFF) << 8)
         | ((uint32_t)(q8(v2) & 0xFF) << 16) | ((uint32_t)(q8(v3) & 0xFF) << 24);
}

__device__ __forceinline__ unsigned int f2ord(float f) {
    unsigned int b = __float_as_uint(f);
    return (b & 0x80000000u) ? ~b : (b | 0x80000000u);
}
__device__ __forceinline__ float ord2f(unsigned int k) {
    unsigned int b = (k & 0x80000000u) ? (k ^ 0x80000000u) : ~k;
    return __uint_as_float(b);
}

// ---------------------------------------------------------------------------
// Kernel 1: fp32 -> int8 quantization + row norms (one warp per row)
// ---------------------------------------------------------------------------
__global__ __launch_bounds__(256) void vq_prep(const float* __restrict__ X,
                                               const float* __restrict__ CB) {
    int row = blockIdx.x * 8 + (threadIdx.x >> 5);
    int lane = threadIdx.x & 31;
    bool isX = row < N_ROWS;
    const float* src = isX ? X + (size_t)row * D_DIM : CB + (size_t)(row - N_ROWS) * D_DIM;
    uint8_t* dst = isX ? g_Xq + (size_t)row * D_DIM : g_Eq + (size_t)(row - N_ROWS) * D_DIM;
    float nrm = 0.0f;
    #pragma unroll
    for (int i = 0; i < 4; ++i) {
        float4 v = reinterpret_cast<const float4*>(src)[lane + i * 32];
        nrm = fmaf(v.x, v.x, nrm); nrm = fmaf(v.y, v.y, nrm);
        nrm = fmaf(v.z, v.z, nrm); nrm = fmaf(v.w, v.w, nrm);
        reinterpret_cast<uint32_t*>(dst)[lane + i * 32] = pack_s8x4(v.x, v.y, v.z, v.w);
    }
    #pragma unroll
    for (int o = 16; o > 0; o >>= 1) nrm += __shfl_down_sync(0xFFFFFFFFu, nrm, o);
    if (lane == 0) {
        if (isX) g_xn[row] = nrm;
        else     g_cbn[row - N_ROWS] = nrm;
    }
}

// ---------------------------------------------------------------------------
// Kernel 2: int8 IMMA GEMM -> per-(row, 32-code group) packed min
// CTA 128x128, 128 threads = 4 warps (2m x 2n), warp tile 64x64.
// BK = 64 int8 bytes per step (8 steps). 3-stage cp.async ring.
// ---------------------------------------------------------------------------
#define BKB      64                      // bytes of K per step
#define ROW_STR  80                      // 64B data + 16B pad
#define TILE_BYTES (128 * ROW_STR)
#define BUF_BYTES  (2 * TILE_BYTES)      // A+B per stage (20KB)
#define NSTAGE   3
#define GEMM_SMEM (NSTAGE * BUF_BYTES)   // 60KB

__global__ __launch_bounds__(128, 2) void vq_gemm() {
    extern __shared__ __align__(128) char smem[];
    const uint32_t sb = smem_u32(smem);
    const int tid = threadIdx.x;
    const int wid = tid >> 5;
    const int lane = tid & 31;
    const int warp_m = wid & 1;
    const int warp_n = wid >> 1;
    const int m0 = blockIdx.x * 128;
    const int n0 = blockIdx.y * 128;

    int acc[4][8][4];
    #pragma unroll
    for (int i = 0; i < 4; ++i)
        #pragma unroll
        for (int j = 0; j < 8; ++j)
            #pragma unroll
            for (int q = 0; q < 4; ++q) acc[i][j][q] = 0;

    // one stage: A 128x64B + B 128x64B, 8 CP16 per thread
    #define PREFETCH(st, k0)                                                          \
    do {                                                                              \
        uint32_t base = sb + (st) * BUF_BYTES;                                        \
        _Pragma("unroll")                                                             \
        for (int i = 0; i < 4; ++i) {                                                 \
            int c = tid + i * 128;                                                    \
            int row = c >> 2, kc = c & 3;                                             \
            CP16(base + row * ROW_STR + kc * 16,                                      \
                 g_Xq + (size_t)(m0 + row) * D_DIM + (k0) + kc * 16);                 \
            CP16(base + TILE_BYTES + row * ROW_STR + kc * 16,                         \
                 g_Eq + (size_t)(n0 + row) * D_DIM + (k0) + kc * 16);                 \
        }                                                                             \
        CP_COMMIT();                                                                  \
    } while (0)

    PREFETCH(0, 0);
    PREFETCH(1, BKB);

    const int NSTEP = D_DIM / BKB;       // 8
    for (int s = 0; s < NSTEP; ++s) {
        if (s < NSTEP - 1) { CP_WAIT1(); } else { CP_WAIT0(); }
        __syncthreads();
        if (s + 2 < NSTEP) PREFETCH((s + 2) % NSTAGE, (s + 2) * BKB);

        const uint32_t abase = sb + (s % NSTAGE) * BUF_BYTES;
        const uint32_t bbase = abase + TILE_BYTES;

        #pragma unroll
        for (int kk = 0; kk < 2; ++kk) {   // two k32 (32B) sub-steps
            uint32_t a[4][4], b[4][4];
            #pragma unroll
            for (int mi = 0; mi < 4; ++mi) {
                uint32_t addr = abase
                    + (uint32_t)(warp_m * 64 + mi * 16 + (lane & 15)) * ROW_STR
                    + (uint32_t)((lane >> 4) + kk * 2) * 16;
                LDSM4(a[mi][0], a[mi][1], a[mi][2], a[mi][3], addr);
            }
            #pragma unroll
            for (int nj = 0; nj < 4; ++nj) {
                uint32_t addr = bbase
                    + (uint32_t)(warp_n * 64 + nj * 16 + (lane & 7) + ((lane >> 4) * 8)) * ROW_STR
                    + (uint32_t)(((lane >> 3) & 1) + kk * 2) * 16;
                LDSM4(b[nj][0], b[nj][1], b[nj][2], b[nj][3], addr);
            }
            #pragma unroll
            for (int mi = 0; mi < 4; ++mi)
                #pragma unroll
                for (int ni = 0; ni < 8; ++ni)
                    IMMA(acc[mi][ni], a[mi],
                         b[ni >> 1][(ni & 1) * 2], b[ni >> 1][(ni & 1) * 2 + 1]);
        }
    }

    // epilogue: per-row min over each of this warp's two 32-col groups
    const int rquad = lane >> 2;
    const int cpair = (lane & 3) * 2;
    #pragma unroll
    for (int mi = 0; mi < 4; ++mi) {
        #pragma unroll
        for (int half = 0; half < 2; ++half) {
            #pragma unroll
            for (int g2 = 0; g2 < 2; ++g2) {
                float best = CUDART_INF_F;
                int bidx = 0;
                #pragma unroll
                for (int nq = 0; nq < 4; ++nq) {
                    int ni = g2 * 4 + nq;
                    int col = n0 + warp_n * 64 + ni * 8 + cpair;
                    float s0 = fmaf(-DEQ2, (float)acc[mi][ni][half * 2 + 0], g_cbn[col]);
                    float s1 = fmaf(-DEQ2, (float)acc[mi][ni][half * 2 + 1], g_cbn[col + 1]);
                    if (s0 < best) { best = s0; bidx = col; }
                    if (s1 < best) { best = s1; bidx = col + 1; }
                }
                unsigned int key = f2ord(best);
                unsigned int idx = (unsigned int)bidx;
                #pragma unroll
                for (int o = 1; o <= 2; o <<= 1) {
                    unsigned int ok = __shfl_xor_sync(0xFFFFFFFFu, key, o);
                    unsigned int oi = __shfl_xor_sync(0xFFFFFFFFu, idx, o);
                    if (ok < key || (ok == key && oi < idx)) { key = ok; idx = oi; }
                }
                if ((lane & 3) == 0) {
                    int row = m0 + warp_m * 64 + mi * 16 + half * 8 + rquad;
                    int gidx = blockIdx.y * 4 + warp_n * 2 + g2;
                    g_gmin[(size_t)row * NGROUPS + gidx] =
                        ((unsigned long long)key << 32) | idx;
                }
            }
        }
    }
}

// ---------------------------------------------------------------------------
// Kernel 3: per-row select — group-min scan + exact fp32 rescore of passing groups
// ---------------------------------------------------------------------------
#define MARGIN  12.0f
#define MAXGRP  64

__global__ __launch_bounds__(256) void vq_select(const float* __restrict__ X,
                                                 const float* __restrict__ CB,
                                                 float* __restrict__ out) {
    __shared__ float xrow[D_DIM];
    __shared__ unsigned long long redm[8];
    __shared__ float redf2[8];
    __shared__ int glist[MAXGRP];
    __shared__ int gcnt;
    __shared__ unsigned long long best;
    __shared__ float thr_sh;

    const int n = blockIdx.x;
    const int t = threadIdx.x;
    const int w = t >> 5;
    const int lane = t & 31;

    float2 xv = reinterpret_cast<const float2*>(X + (size_t)n * D_DIM)[t];
    xrow[2 * t] = xv.x;
    xrow[2 * t + 1] = xv.y;
    if (t == 0) { gcnt = 0; best = 0xFFFFFFFFFFFFFFFFull; }

    unsigned long long p = g_gmin[(size_t)n * NGROUPS + t];
    unsigned long long q = p;
    #pragma unroll
    for (int o = 16; o > 0; o >>= 1) {
        unsigned long long v = __shfl_down_sync(0xFFFFFFFFu, q, o);
        if (v < q) q = v;
    }
    if (lane == 0) redm[w] = q;
    __syncthreads();
    if (t == 0) {
        unsigned long long m = redm[0];
        #pragma unroll
        for (int i = 1; i < 8; ++i) if (redm[i] < m) m = redm[i];
        thr_sh = ord2f((unsigned int)(m >> 32)) + MARGIN;
    }
    __syncthreads();
    if (ord2f((unsigned int)(p >> 32)) <= thr_sh) {
        int pos = atomicAdd(&gcnt, 1);
        if (pos < MAXGRP) glist[pos] = t;
    }
    __syncthreads();
    const int ng = min(gcnt, MAXGRP);

    const float4* x4 = reinterpret_cast<const float4*>(xrow);
    for (int gi = 0; gi < ng; ++gi) {
        const int g = glist[gi];
        #pragma unroll
        for (int cc = 0; cc < 4; ++cc) {
            const int j = g * 32 + w * 4 + cc;
            const float4* er = reinterpret_cast<const float4*>(CB + (size_t)j * D_DIM);
            float dot = 0.0f;
            #pragma unroll
            for (int i = 0; i < 4; ++i) {
                float4 e = er[lane + i * 32];
                float4 x = x4[lane + i * 32];
                dot = fmaf(x.x, e.x, dot);
                dot = fmaf(x.y, e.y, dot);
                dot = fmaf(x.z, e.z, dot);
                dot = fmaf(x.w, e.w, dot);
            }
            #pragma unroll
            for (int o = 16; o > 0; o >>= 1) dot += __shfl_down_sync(0xFFFFFFFFu, dot, o);
            if (lane == 0) {
                float s = fmaf(-2.0f, dot, g_cbn[j]);
                unsigned long long pk =
                    ((unsigned long long)f2ord(s) << 32) | (unsigned int)j;
                atomicMin(&best, pk);
            }
        }
    }
    __syncthreads();

    const unsigned long long bw = best;
    const int jstar = (int)(bw & 0xFFFFFFFFull);
    const float sstar = ord2f((unsigned int)(bw >> 32));

    float2 q2 = reinterpret_cast<const float2*>(CB + (size_t)jstar * D_DIM)[t];
    reinterpret_cast<float2*>(out + QUANT_OFF)[(size_t)n * (D_DIM / 2) + t] = q2;
    float d0 = xrow[2 * t] - q2.x;
    float d1 = xrow[2 * t + 1] - q2.y;
    float dl = fmaf(d0, d0, d1 * d1);
    #pragma unroll
    for (int o = 16; o > 0; o >>= 1) dl += __shfl_down_sync(0xFFFFFFFFu, dl, o);
    if (lane == 0) redf2[w] = dl;
    __syncthreads();
    if (t == 0) {
        float DL = redf2[0] + redf2[1] + redf2[2] + redf2[3]
                 + redf2[4] + redf2[5] + redf2[6] + redf2[7];
        g_row_partial[n] = DL;
        out[MIND_OFF + n] = g_xn[n] + sstar;
        out[IDX_OFF + n] = (float)jstar;
    }
}

// ---------------------------------------------------------------------------
// Kernel 4: final loss reduction
// ---------------------------------------------------------------------------
__global__ __launch_bounds__(256) void vq_loss(float* __restrict__ out) {
    __shared__ float red[256];
    int t = threadIdx.x;
    float s = 0.0f;
    for (int i = t; i < N_ROWS; i += 256) s += g_row_partial[i];
    red[t] = s;
    __syncthreads();
    #pragma unroll
    for (int o = 128; o > 0; o >>= 1) {
        if (t < o) red[t] += red[t + o];
        __syncthreads();
    }
    if (t == 0) {
        float S = red[0];
        out[COMMIT_OFF] = S;
        out[LOSS_OFF]   = fmaf(0.25f, S, S);
    }
}

// ---------------------------------------------------------------------------
extern "C" void kernel_launch(void* const* d_in, const int* in_sizes, int n_in,
                              void* d_out, int out_size) {
    const float* X  = (const float*)d_in[0];
    const float* CB = (const float*)d_in[1];
    float* out = (float*)d_out;

    cudaFuncSetAttribute(vq_gemm, cudaFuncAttributeMaxDynamicSharedMemorySize, GEMM_SMEM);

    vq_prep<<<(N_ROWS + K_CODES) / 8, 256>>>(X, CB);
    vq_gemm<<<dim3(64, 64), 128, GEMM_SMEM>>>();
    vq_select<<<N_ROWS, 256>>>(X, CB, out);
    vq_loss<<<1, 256>>>(out);
}

// round 9
// speedup vs baseline: 2.0713x; 2.0713x over previous
#include <cuda_runtime.h>
#include <cuda_fp16.h>
#include <cstdint>
#include <math_constants.h>

#define N_ROWS   8192
#define K_CODES  8192
#define D_DIM    512
#define NGROUPS  (K_CODES / 32)    // 256 column groups of 32 codes

// Output layout: [quantized (4194304) | loss (1) | indices (8192) | min_dist (8192) | loss_commit (1)]
#define QUANT_OFF  0
#define LOSS_OFF   (N_ROWS * D_DIM)
#define IDX_OFF    (LOSS_OFF + 1)
#define MIND_OFF   (IDX_OFF + N_ROWS)
#define COMMIT_OFF (MIND_OFF + N_ROWS)

// ---------------- device scratch ----------------
__device__ __half g_Xh[N_ROWS * D_DIM];      // f16 inputs
__device__ __half g_Eh[K_CODES * D_DIM];     // f16 codebook
__device__ unsigned long long g_gmin[(size_t)N_ROWS * NGROUPS];  // 16MB packed (score,idx)
__device__ float g_cbn[K_CODES];
__device__ float g_xn[N_ROWS];
__device__ float g_row_partial[N_ROWS];

// ---------------- helpers ----------------
__device__ __forceinline__ uint32_t smem_u32(const void* p) {
    uint32_t a;
    asm("{ .reg .u64 t; cvta.to.shared.u64 t, %1; cvt.u32.u64 %0, t; }" : "=r"(a) : "l"(p));
    return a;
}
#define CP16(dst, src) \
    asm volatile("cp.async.cg.shared.global [%0], [%1], 16;" :: "r"(dst), "l"(src))
#define CP_COMMIT() asm volatile("cp.async.commit_group;" ::: "memory")
#define CP_WAIT1()  asm volatile("cp.async.wait_group 1;" ::: "memory")
#define CP_WAIT0()  asm volatile("cp.async.wait_group 0;" ::: "memory")

#define LDSM4(r0, r1, r2, r3, addr) \
    asm volatile("ldmatrix.sync.aligned.m8n8.x4.shared.b16 {%0,%1,%2,%3}, [%4];" \
        : "=r"(r0), "=r"(r1), "=r"(r2), "=r"(r3) : "r"(addr))

// classic f16-accumulate HMMA (2 output regs = 4 halves)
#define MMAF16(c, a, b0, b1) \
    asm volatile("mma.sync.aligned.m16n8k16.row.col.f16.f16.f16.f16 " \
        "{%0,%1}, {%2,%3,%4,%5}, {%6,%7}, {%0,%1};" \
        : "+r"((c)[0]), "+r"((c)[1]) \
        : "r"((a)[0]), "r"((a)[1]), "r"((a)[2]), "r"((a)[3]), "r"(b0), "r"(b1))

__device__ __forceinline__ unsigned int f2ord(float f) {
    unsigned int b = __float_as_uint(f);
    return (b & 0x80000000u) ? ~b : (b | 0x80000000u);
}
__device__ __forceinline__ float ord2f(unsigned int k) {
    unsigned int b = (k & 0x80000000u) ? (k ^ 0x80000000u) : ~k;
    return __uint_as_float(b);
}

// ---------------------------------------------------------------------------
// Kernel 1: fp32 -> f16 conversion + row norms (one warp per row)
// ---------------------------------------------------------------------------
__global__ __launch_bounds__(256) void vq_prep(const float* __restrict__ X,
                                               const float* __restrict__ CB) {
    int row = blockIdx.x * 8 + (threadIdx.x >> 5);
    int lane = threadIdx.x & 31;
    bool isX = row < N_ROWS;
    const float* src = isX ? X + (size_t)row * D_DIM : CB + (size_t)(row - N_ROWS) * D_DIM;
    __half* dst = isX ? g_Xh + (size_t)row * D_DIM : g_Eh + (size_t)(row - N_ROWS) * D_DIM;
    float nrm = 0.0f;
    #pragma unroll
    for (int i = 0; i < 4; ++i) {
        float4 v = reinterpret_cast<const float4*>(src)[lane + i * 32];
        nrm = fmaf(v.x, v.x, nrm); nrm = fmaf(v.y, v.y, nrm);
        nrm = fmaf(v.z, v.z, nrm); nrm = fmaf(v.w, v.w, nrm);
        __half2 h0 = __floats2half2_rn(v.x, v.y);
        __half2 h1 = __floats2half2_rn(v.z, v.w);
        uint2 pk;
        pk.x = *reinterpret_cast<uint32_t*>(&h0);
        pk.y = *reinterpret_cast<uint32_t*>(&h1);
        reinterpret_cast<uint2*>(dst)[lane + i * 32] = pk;
    }
    #pragma unroll
    for (int o = 16; o > 0; o >>= 1) nrm += __shfl_down_sync(0xFFFFFFFFu, nrm, o);
    if (lane == 0) {
        if (isX) g_xn[row] = nrm;
        else     g_cbn[row - N_ROWS] = nrm;
    }
}

// ---------------------------------------------------------------------------
// Kernel 2: f16 HMMA GEMM (f16 accum) -> per-(row, 32-code group) packed min
// CTA 128x128, 128 threads = 4 warps (2m x 2n), warp tile 64x64.
// 3-stage cp.async ring, one __syncthreads per K-step. Layout identical to R6.
// ---------------------------------------------------------------------------
#define BKB      32                      // K elements per step (64B rows)
#define ROW_STR  80
#define TILE_BYTES (128 * ROW_STR)
#define BUF_BYTES  (2 * TILE_BYTES)
#define NSTAGE   3
#define GEMM_SMEM (NSTAGE * BUF_BYTES)   // 60KB

__global__ __launch_bounds__(128, 2) void vq_gemm() {
    extern __shared__ __align__(128) char smem[];
    const uint32_t sb = smem_u32(smem);
    const int tid = threadIdx.x;
    const int wid = tid >> 5;
    const int lane = tid & 31;
    const int warp_m = wid & 1;
    const int warp_n = wid >> 1;
    const int m0 = blockIdx.x * 128;
    const int n0 = blockIdx.y * 128;

    uint32_t acc[4][8][2];
    #pragma unroll
    for (int i = 0; i < 4; ++i)
        #pragma unroll
        for (int j = 0; j < 8; ++j) { acc[i][j][0] = 0u; acc[i][j][1] = 0u; }

    #define PREFETCH(st, k0)                                                          \
    do {                                                                              \
        uint32_t base = sb + (st) * BUF_BYTES;                                        \
        _Pragma("unroll")                                                             \
        for (int i = 0; i < 4; ++i) {                                                 \
            int c = tid + i * 128;                                                    \
            int row = c >> 2, kc = c & 3;                                             \
            CP16(base + row * ROW_STR + kc * 16,                                      \
                 g_Xh + (size_t)(m0 + row) * D_DIM + (k0) + kc * 8);                  \
            CP16(base + TILE_BYTES + row * ROW_STR + kc * 16,                         \
                 g_Eh + (size_t)(n0 + row) * D_DIM + (k0) + kc * 8);                  \
        }                                                                             \
        CP_COMMIT();                                                                  \
    } while (0)

    PREFETCH(0, 0);
    PREFETCH(1, BKB);

    const int NSTEP = D_DIM / BKB;       // 16
    for (int s = 0; s < NSTEP; ++s) {
        if (s < NSTEP - 1) { CP_WAIT1(); } else { CP_WAIT0(); }
        __syncthreads();
        if (s + 2 < NSTEP) PREFETCH((s + 2) % NSTAGE, (s + 2) * BKB);

        const uint32_t abase = sb + (s % NSTAGE) * BUF_BYTES;
        const uint32_t bbase = abase + TILE_BYTES;

        #pragma unroll
        for (int kk = 0; kk < 2; ++kk) {
            uint32_t a[4][4], b[4][4];
            #pragma unroll
            for (int mi = 0; mi < 4; ++mi) {
                uint32_t addr = abase
                    + (uint32_t)(warp_m * 64 + mi * 16 + (lane & 15)) * ROW_STR
                    + (uint32_t)((lane >> 4) + kk * 2) * 16;
                LDSM4(a[mi][0], a[mi][1], a[mi][2], a[mi][3], addr);
            }
            #pragma unroll
            for (int nj = 0; nj < 4; ++nj) {
                uint32_t addr = bbase
                    + (uint32_t)(warp_n * 64 + nj * 16 + (lane & 7) + ((lane >> 4) * 8)) * ROW_STR
                    + (uint32_t)(((lane >> 3) & 1) + kk * 2) * 16;
                LDSM4(b[nj][0], b[nj][1], b[nj][2], b[nj][3], addr);
            }
            #pragma unroll
            for (int mi = 0; mi < 4; ++mi)
                #pragma unroll
                for (int ni = 0; ni < 8; ++ni)
                    MMAF16(acc[mi][ni], a[mi],
                           b[ni >> 1][(ni & 1) * 2], b[ni >> 1][(ni & 1) * 2 + 1]);
        }
    }

    // epilogue: per-row min over each of this warp's two 32-col groups.
    // acc reg 'half': 0 -> rows (lane>>2), 1 -> rows (lane>>2)+8; halves = cols pair.
    const int rquad = lane >> 2;
    const int cpair = (lane & 3) * 2;
    #pragma unroll
    for (int mi = 0; mi < 4; ++mi) {
        #pragma unroll
        for (int half = 0; half < 2; ++half) {
            #pragma unroll
            for (int g2 = 0; g2 < 2; ++g2) {
                float best = CUDART_INF_F;
                int bidx = 0;
                #pragma unroll
                for (int nq = 0; nq < 4; ++nq) {
                    int ni = g2 * 4 + nq;
                    int col = n0 + warp_n * 64 + ni * 8 + cpair;
                    float2 d01 = __half22float2(
                        *reinterpret_cast<const __half2*>(&acc[mi][ni][half]));
                    float s0 = fmaf(-2.0f, d01.x, g_cbn[col]);
                    float s1 = fmaf(-2.0f, d01.y, g_cbn[col + 1]);
                    if (s0 < best) { best = s0; bidx = col; }
                    if (s1 < best) { best = s1; bidx = col + 1; }
                }
                unsigned int key = f2ord(best);
                unsigned int idx = (unsigned int)bidx;
                #pragma unroll
                for (int o = 1; o <= 2; o <<= 1) {
                    unsigned int ok = __shfl_xor_sync(0xFFFFFFFFu, key, o);
                    unsigned int oi = __shfl_xor_sync(0xFFFFFFFFu, idx, o);
                    if (ok < key || (ok == key && oi < idx)) { key = ok; idx = oi; }
                }
                if ((lane & 3) == 0) {
                    int row = m0 + warp_m * 64 + mi * 16 + half * 8 + rquad;
                    int gidx = blockIdx.y * 4 + warp_n * 2 + g2;
                    g_gmin[(size_t)row * NGROUPS + gidx] =
                        ((unsigned long long)key << 32) | idx;
                }
            }
        }
    }
}

// ---------------------------------------------------------------------------
// Kernel 3: per-row select — group-min scan + exact fp32 rescore of passing groups
// ---------------------------------------------------------------------------
#define MARGIN  8.0f
#define MAXGRP  64

__global__ __launch_bounds__(256) void vq_select(const float* __restrict__ X,
                                                 const float* __restrict__ CB,
                                                 float* __restrict__ out) {
    __shared__ float xrow[D_DIM];
    __shared__ unsigned long long redm[8];
    __shared__ float redf2[8];
    __shared__ int glist[MAXGRP];
    __shared__ int gcnt;
    __shared__ unsigned long long best;
    __shared__ float thr_sh;

    const int n = blockIdx.x;
    const int t = threadIdx.x;
    const int w = t >> 5;
    const int lane = t & 31;

    float2 xv = reinterpret_cast<const float2*>(X + (size_t)n * D_DIM)[t];
    xrow[2 * t] = xv.x;
    xrow[2 * t + 1] = xv.y;
    if (t == 0) { gcnt = 0; best = 0xFFFFFFFFFFFFFFFFull; }

    unsigned long long p = g_gmin[(size_t)n * NGROUPS + t];
    unsigned long long q = p;
    #pragma unroll
    for (int o = 16; o > 0; o >>= 1) {
        unsigned long long v = __shfl_down_sync(0xFFFFFFFFu, q, o);
        if (v < q) q = v;
    }
    if (lane == 0) redm[w] = q;
    __syncthreads();
    if (t == 0) {
        unsigned long long m = redm[0];
        #pragma unroll
        for (int i = 1; i < 8; ++i) if (redm[i] < m) m = redm[i];
        thr_sh = ord2f((unsigned int)(m >> 32)) + MARGIN;
    }
    __syncthreads();
    if (ord2f((unsigned int)(p >> 32)) <= thr_sh) {
        int pos = atomicAdd(&gcnt, 1);
        if (pos < MAXGRP) glist[pos] = t;
    }
    __syncthreads();
    const int ng = min(gcnt, MAXGRP);

    const float4* x4 = reinterpret_cast<const float4*>(xrow);
    for (int gi = 0; gi < ng; ++gi) {
        const int g = glist[gi];
        #pragma unroll
        for (int cc = 0; cc < 4; ++cc) {
            const int j = g * 32 + w * 4 + cc;
            const float4* er = reinterpret_cast<const float4*>(CB + (size_t)j * D_DIM);
            float dot = 0.0f;
            #pragma unroll
            for (int i = 0; i < 4; ++i) {
                float4 e = er[lane + i * 32];
                float4 x = x4[lane + i * 32];
                dot = fmaf(x.x, e.x, dot);
                dot = fmaf(x.y, e.y, dot);
                dot = fmaf(x.z, e.z, dot);
                dot = fmaf(x.w, e.w, dot);
            }
            #pragma unroll
            for (int o = 16; o > 0; o >>= 1) dot += __shfl_down_sync(0xFFFFFFFFu, dot, o);
            if (lane == 0) {
                float s = fmaf(-2.0f, dot, g_cbn[j]);
                unsigned long long pk =
                    ((unsigned long long)f2ord(s) << 32) | (unsigned int)j;
                atomicMin(&best, pk);
            }
        }
    }
    __syncthreads();

    const unsigned long long bw = best;
    const int jstar = (int)(bw & 0xFFFFFFFFull);
    const float sstar = ord2f((unsigned int)(bw >> 32));

    float2 q2 = reinterpret_cast<const float2*>(CB + (size_t)jstar * D_DIM)[t];
    reinterpret_cast<float2*>(out + QUANT_OFF)[(size_t)n * (D_DIM / 2) + t] = q2;
    float d0 = xrow[2 * t] - q2.x;
    float d1 = xrow[2 * t + 1] - q2.y;
    float dl = fmaf(d0, d0, d1 * d1);
    #pragma unroll
    for (int o = 16; o > 0; o >>= 1) dl += __shfl_down_sync(0xFFFFFFFFu, dl, o);
    if (lane == 0) redf2[w] = dl;
    __syncthreads();
    if (t == 0) {
        float DL = redf2[0] + redf2[1] + redf2[2] + redf2[3]
                 + redf2[4] + redf2[5] + redf2[6] + redf2[7];
        g_row_partial[n] = DL;
        out[MIND_OFF + n] = g_xn[n] + sstar;
        out[IDX_OFF + n] = (float)jstar;
    }
}

// ---------------------------------------------------------------------------
// Kernel 4: final loss reduction
// ---------------------------------------------------------------------------
__global__ __launch_bounds__(256) void vq_loss(float* __restrict__ out) {
    __shared__ float red[256];
    int t = threadIdx.x;
    float s = 0.0f;
    for (int i = t; i < N_ROWS; i += 256) s += g_row_partial[i];
    red[t] = s;
    __syncthreads();
    #pragma unroll
    for (int o = 128; o > 0; o >>= 1) {
        if (t < o) red[t] += red[t + o];
        __syncthreads();
    }
    if (t == 0) {
        float S = red[0];
        out[COMMIT_OFF] = S;
        out[LOSS_OFF]   = fmaf(0.25f, S, S);
    }
}

// ---------------------------------------------------------------------------
extern "C" void kernel_launch(void* const* d_in, const int* in_sizes, int n_in,
                              void* d_out, int out_size) {
    const float* X  = (const float*)d_in[0];
    const float* CB = (const float*)d_in[1];
    float* out = (float*)d_out;

    cudaFuncSetAttribute(vq_gemm, cudaFuncAttributeMaxDynamicSharedMemorySize, GEMM_SMEM);

    vq_prep<<<(N_ROWS + K_CODES) / 8, 256>>>(X, CB);
    vq_gemm<<<dim3(64, 64), 128, GEMM_SMEM>>>();
    vq_select<<<N_ROWS, 256>>>(X, CB, out);
    vq_loss<<<1, 256>>>(out);
}